// round 2
// baseline (speedup 1.0000x reference)
#include <cuda_runtime.h>
#include <cuda_bf16.h>
#include <cstdint>
#include <cstddef>

// ---------------------------------------------------------------------------
// LlamaDecoderLayer: B=1, T=2048, D=2048, NH=32, NKV=8, HD=64, FF=8192, fp32
//
// h1  = rmsnorm(x, g1)
// h2  = h1 + attn(h1) @ wo          (attn = causal GQA flash attention + RoPE)
// h3  = rmsnorm(h2, g2)
// out = h3 + (silu(h3@wg) * (h3@wu)) @ wd + x
// ---------------------------------------------------------------------------

#define T_LEN 2048
#define DMODEL 2048
#define NHEAD 32
#define NKV 8
#define HD 64
#define KVD 512   // NKV*HD
#define FF 8192

// ---- scratch (static device globals; no allocation in kernel_launch) ------
__device__ float g_xn [T_LEN * DMODEL];   // h1
__device__ float g_q  [T_LEN * DMODEL];
__device__ float g_k  [T_LEN * KVD];
__device__ float g_v  [T_LEN * KVD];
__device__ float g_att[T_LEN * DMODEL];   // attention output (pre-wo)
__device__ float g_h2 [T_LEN * DMODEL];
__device__ float g_h3 [T_LEN * DMODEL];
__device__ float g_gb [T_LEN * FF];       // gate, then silu(gate)*up
__device__ float g_ub [T_LEN * FF];       // up

// ---------------------------------------------------------------------------
// RMSNorm: one block per row, 256 threads
// ---------------------------------------------------------------------------
__global__ __launch_bounds__(256) void rmsnorm_k(const float* __restrict__ x,
                                                 const float* __restrict__ g,
                                                 float* __restrict__ out)
{
    int row = blockIdx.x;
    int tid = threadIdx.x;
    const float4* xr4 = (const float4*)(x + (size_t)row * DMODEL);
    const float4* g4  = (const float4*)g;
    float4*       o4  = (float4*)(out + (size_t)row * DMODEL);

    float4 a = xr4[tid];
    float4 b = xr4[tid + 256];
    float s = a.x*a.x + a.y*a.y + a.z*a.z + a.w*a.w
            + b.x*b.x + b.y*b.y + b.z*b.z + b.w*b.w;

    #pragma unroll
    for (int off = 16; off > 0; off >>= 1)
        s += __shfl_xor_sync(0xffffffffu, s, off);

    __shared__ float red[8];
    __shared__ float inv_s;
    int wid = tid >> 5, lane = tid & 31;
    if (lane == 0) red[wid] = s;
    __syncthreads();
    if (tid == 0) {
        float t = 0.f;
        #pragma unroll
        for (int w = 0; w < 8; w++) t += red[w];
        inv_s = rsqrtf(t / (float)DMODEL + 1e-5f);
    }
    __syncthreads();
    float inv = inv_s;

    float4 ga = g4[tid], gb = g4[tid + 256];
    float4 ra, rb;
    ra.x = a.x*ga.x*inv; ra.y = a.y*ga.y*inv; ra.z = a.z*ga.z*inv; ra.w = a.w*ga.w*inv;
    rb.x = b.x*gb.x*inv; rb.y = b.y*gb.y*inv; rb.z = b.z*gb.z*inv; rb.w = b.w*gb.w*inv;
    o4[tid] = ra;
    o4[tid + 256] = rb;
}

// ---------------------------------------------------------------------------
// SGEMM: C[M,N] = A[M,K] @ B[K,N] (+ add0 + add1), all row-major fp32.
// 128x128 block tile, BK=8, 256 threads, 8x8 per thread.
// ---------------------------------------------------------------------------
#define BM 128
#define BN 128
#define BK 8

__global__ __launch_bounds__(256) void sgemm_k(const float* __restrict__ A,
                                               const float* __restrict__ B,
                                               float* __restrict__ C,
                                               int M, int N, int K,
                                               const float* __restrict__ add0,
                                               const float* __restrict__ add1)
{
    __shared__ float As[BK][BM];
    __shared__ float Bs[BK][BN];

    int tid  = threadIdx.x;
    int brow = blockIdx.y * BM;
    int bcol = blockIdx.x * BN;

    // A tile load: 128 rows x 8 cols, one float4 per thread
    int arow = tid >> 1;            // 0..127
    int acol = (tid & 1) * 4;       // 0 or 4
    // B tile load: 8 rows x 128 cols, one float4 per thread
    int bkr  = tid >> 5;            // 0..7
    int bnc  = (tid & 31) * 4;      // 0..124

    const float* Aptr = A + (size_t)(brow + arow) * K + acol;
    const float* Bptr = B + (size_t)bkr * N + bcol + bnc;

    int ty = tid >> 4;              // 0..15 -> row group
    int tx = tid & 15;              // 0..15 -> col group

    float acc[8][8];
    #pragma unroll
    for (int i = 0; i < 8; i++)
        #pragma unroll
        for (int j = 0; j < 8; j++) acc[i][j] = 0.f;

    for (int k0 = 0; k0 < K; k0 += BK) {
        float4 a4 = *(const float4*)Aptr;
        float4 b4 = *(const float4*)Bptr;
        Aptr += BK;
        Bptr += (size_t)BK * N;

        As[acol + 0][arow] = a4.x;
        As[acol + 1][arow] = a4.y;
        As[acol + 2][arow] = a4.z;
        As[acol + 3][arow] = a4.w;
        *(float4*)&Bs[bkr][bnc] = b4;
        __syncthreads();

        #pragma unroll
        for (int kk = 0; kk < BK; kk++) {
            float areg[8], breg[8];
            #pragma unroll
            for (int i = 0; i < 8; i++) areg[i] = As[kk][ty * 8 + i];
            #pragma unroll
            for (int j = 0; j < 8; j++) breg[j] = Bs[kk][tx * 8 + j];
            #pragma unroll
            for (int i = 0; i < 8; i++)
                #pragma unroll
                for (int j = 0; j < 8; j++)
                    acc[i][j] += areg[i] * breg[j];
        }
        __syncthreads();
    }

    #pragma unroll
    for (int i = 0; i < 8; i++) {
        int r = brow + ty * 8 + i;
        size_t base = (size_t)r * N + bcol + tx * 8;
        #pragma unroll
        for (int j = 0; j < 8; j++) {
            float val = acc[i][j];
            if (add0) val += add0[base + j];
            if (add1) val += add1[base + j];
            C[base + j] = val;
        }
    }
}

// ---------------------------------------------------------------------------
// RoPE (in-place on q [T, 32*64] and k [T, 8*64])
// ---------------------------------------------------------------------------
__global__ __launch_bounds__(256) void rope_k(float* __restrict__ q,
                                              float* __restrict__ k)
{
    __shared__ float cs[32], sn[32];
    int t = blockIdx.x;
    if (threadIdx.x < 32) {
        int d = threadIdx.x;
        // inv_freq = theta^(-2d/HD); angle = t * inv_freq (double for accuracy)
        double freq = exp((double)(-2.0 * d / 64.0) * 9.210340371976184); // ln(1e4)
        double ang  = freq * (double)t;
        double si, co;
        sincos(ang, &si, &co);
        cs[d] = (float)co;
        sn[d] = (float)si;
    }
    __syncthreads();

    const int NPAIR_Q = NHEAD * (HD / 2);   // 1024
    const int NPAIR_K = NKV  * (HD / 2);    // 256
    for (int p = threadIdx.x; p < NPAIR_Q + NPAIR_K; p += blockDim.x) {
        float* ptr;
        int d;
        if (p < NPAIR_Q) {
            int head = p >> 5; d = p & 31;
            ptr = q + (size_t)t * DMODEL + head * HD + 2 * d;
        } else {
            int pk = p - NPAIR_Q;
            int head = pk >> 5; d = pk & 31;
            ptr = k + (size_t)t * KVD + head * HD + 2 * d;
        }
        float x1 = ptr[0], x2 = ptr[1];
        float c = cs[d], s = sn[d];
        ptr[0] = x1 * c - x2 * s;
        ptr[1] = x2 * c + x1 * s;
    }
}

// ---------------------------------------------------------------------------
// Flash attention (causal, GQA 4:1). grid = (T/64 q-tiles, 32 heads),
// 64 threads: one thread per q row, q row in registers, K/V/S in smem,
// online softmax, only tiles jt <= qt are visited (causal skip).
// ---------------------------------------------------------------------------
__global__ __launch_bounds__(64) void attn_k(const float* __restrict__ Q,
                                             const float* __restrict__ K,
                                             const float* __restrict__ V,
                                             float* __restrict__ O)
{
    __shared__ float k_s[64][64];
    __shared__ float v_s[64][64];
    __shared__ float s_s[64][64];   // [c][row] — conflict-free both ways

    int tid = threadIdx.x;
    int qt  = blockIdx.x;
    int h   = blockIdx.y;
    int kvh = h >> 2;
    int r   = qt * 64 + tid;

    // q row -> registers
    float qreg[64];
    {
        const float4* qp = (const float4*)(Q + (size_t)r * DMODEL + h * HD);
        #pragma unroll
        for (int i = 0; i < 16; i++) {
            float4 t4 = qp[i];
            qreg[4*i+0] = t4.x; qreg[4*i+1] = t4.y;
            qreg[4*i+2] = t4.z; qreg[4*i+3] = t4.w;
        }
    }

    float o[64];
    #pragma unroll
    for (int d = 0; d < 64; d++) o[d] = 0.f;
    float m = -3e38f, l = 0.f;

    for (int jt = 0; jt <= qt; jt++) {
        // load K,V tile (64 kv rows x 64 dims), coalesced: col = tid
        const float* kp = K + (size_t)(jt * 64) * KVD + kvh * HD;
        const float* vp = V + (size_t)(jt * 64) * KVD + kvh * HD;
        #pragma unroll 4
        for (int it = 0; it < 64; it++) {
            k_s[it][tid] = kp[(size_t)it * KVD + tid];
            v_s[it][tid] = vp[(size_t)it * KVD + tid];
        }
        __syncthreads();

        bool dtile = (jt == qt);
        float mx = m;
        #pragma unroll 1
        for (int c = 0; c < 64; c++) {
            float acc = 0.f;
            #pragma unroll
            for (int kk = 0; kk < 64; kk++) acc += qreg[kk] * k_s[c][kk];
            acc *= 0.125f;                               // 1/sqrt(64)
            if (dtile && (jt * 64 + c) > r) acc = -1e30f; // causal mask
            s_s[c][tid] = acc;
            mx = fmaxf(mx, acc);
        }

        float corr = __expf(m - mx);
        m = mx;
        l *= corr;
        #pragma unroll
        for (int d = 0; d < 64; d++) o[d] *= corr;

        #pragma unroll 1
        for (int c = 0; c < 64; c++) {
            float p = __expf(s_s[c][tid] - mx);
            l += p;
            #pragma unroll
            for (int d = 0; d < 64; d++) o[d] += p * v_s[c][d];
        }
        __syncthreads();
    }

    float inv = 1.0f / l;
    float4* op = (float4*)(O + (size_t)r * DMODEL + h * HD);
    #pragma unroll
    for (int i = 0; i < 16; i++)
        op[i] = make_float4(o[4*i+0]*inv, o[4*i+1]*inv, o[4*i+2]*inv, o[4*i+3]*inv);
}

// ---------------------------------------------------------------------------
// silu(g) * u, in place into g. n4 = element count / 4.
// ---------------------------------------------------------------------------
__global__ __launch_bounds__(256) void silu_mul_k(float* __restrict__ g,
                                                  const float* __restrict__ u,
                                                  int n4)
{
    int i = blockIdx.x * blockDim.x + threadIdx.x;
    if (i >= n4) return;
    float4 a = ((float4*)g)[i];
    float4 b = ((const float4*)u)[i];
    a.x = a.x / (1.f + __expf(-a.x)) * b.x;
    a.y = a.y / (1.f + __expf(-a.y)) * b.y;
    a.z = a.z / (1.f + __expf(-a.z)) * b.z;
    a.w = a.w / (1.f + __expf(-a.w)) * b.w;
    ((float4*)g)[i] = a;
}

// ---------------------------------------------------------------------------
// kernel_launch
// ---------------------------------------------------------------------------
extern "C" void kernel_launch(void* const* d_in, const int* in_sizes, int n_in,
                              void* d_out, int out_size)
{
    (void)in_sizes; (void)n_in; (void)out_size;
    const float* x  = (const float*)d_in[0];
    const float* g1 = (const float*)d_in[1];
    const float* wq = (const float*)d_in[2];
    const float* wk = (const float*)d_in[3];
    const float* wv = (const float*)d_in[4];
    const float* wo = (const float*)d_in[5];
    const float* g2 = (const float*)d_in[6];
    const float* wg = (const float*)d_in[7];
    const float* wu = (const float*)d_in[8];
    const float* wd = (const float*)d_in[9];
    float* out = (float*)d_out;

    float *xn, *q, *k, *v, *att, *h2, *h3, *gb, *ub;
    cudaGetSymbolAddress((void**)&xn,  g_xn);
    cudaGetSymbolAddress((void**)&q,   g_q);
    cudaGetSymbolAddress((void**)&k,   g_k);
    cudaGetSymbolAddress((void**)&v,   g_v);
    cudaGetSymbolAddress((void**)&att, g_att);
    cudaGetSymbolAddress((void**)&h2,  g_h2);
    cudaGetSymbolAddress((void**)&h3,  g_h3);
    cudaGetSymbolAddress((void**)&gb,  g_gb);
    cudaGetSymbolAddress((void**)&ub,  g_ub);

    // h1 = rmsnorm(x, g1)
    rmsnorm_k<<<T_LEN, 256>>>(x, g1, xn);

    // q, k, v projections
    sgemm_k<<<dim3(DMODEL / BN, T_LEN / BM), 256>>>(xn, wq, q, T_LEN, DMODEL, DMODEL, nullptr, nullptr);
    sgemm_k<<<dim3(KVD   / BN, T_LEN / BM), 256>>>(xn, wk, k, T_LEN, KVD,    DMODEL, nullptr, nullptr);
    sgemm_k<<<dim3(KVD   / BN, T_LEN / BM), 256>>>(xn, wv, v, T_LEN, KVD,    DMODEL, nullptr, nullptr);

    // RoPE on q and k
    rope_k<<<T_LEN, 256>>>(q, k);

    // causal GQA attention
    attn_k<<<dim3(T_LEN / 64, NHEAD), 64>>>(q, k, v, att);

    // h2 = h1 + att @ wo
    sgemm_k<<<dim3(DMODEL / BN, T_LEN / BM), 256>>>(att, wo, h2, T_LEN, DMODEL, DMODEL, xn, nullptr);

    // h3 = rmsnorm(h2, g2)
    rmsnorm_k<<<T_LEN, 256>>>(h2, g2, h3);

    // gate / up
    sgemm_k<<<dim3(FF / BN, T_LEN / BM), 256>>>(h3, wg, gb, T_LEN, FF, DMODEL, nullptr, nullptr);
    sgemm_k<<<dim3(FF / BN, T_LEN / BM), 256>>>(h3, wu, ub, T_LEN, FF, DMODEL, nullptr, nullptr);

    // gb = silu(gb) * ub
    int n4 = T_LEN * FF / 4;
    silu_mul_k<<<(n4 + 255) / 256, 256>>>(gb, ub, n4);

    // out = gb @ wd + h3 + x
    sgemm_k<<<dim3(DMODEL / BN, T_LEN / BM), 256>>>(gb, wd, out, T_LEN, DMODEL, FF, h3, x);
}

// round 4
// speedup vs baseline: 2.4095x; 2.4095x over previous
#include <cuda_runtime.h>
#include <cstdint>
#include <cstddef>

// ---------------------------------------------------------------------------
// LlamaDecoderLayer fp32. GEMMs via portable mma.sync tf32 (compute_103-safe).
// T=2048, D=2048, NH=32, NKV=8, HD=64, FF=8192.
// ---------------------------------------------------------------------------

#define T_LEN 2048
#define DMODEL 2048
#define NHEAD 32
#define NKV 8
#define HD 64
#define FF 8192
#define QKV_N 3072          // 2048 q + 512 k + 512 v
#define GU_N  16384         // gate 8192 + up 8192

// ---- scratch -------------------------------------------------------------
__device__ float g_xn  [T_LEN * DMODEL];     // h1 exact (residual)
__device__ float g_xnt [T_LEN * DMODEL];     // h1 tf32-rounded (GEMM A)
__device__ float g_qkv [T_LEN * QKV_N];
__device__ float g_att [T_LEN * DMODEL];     // attention out, tf32-rounded
__device__ float g_h2  [T_LEN * DMODEL];
__device__ float g_h3  [T_LEN * DMODEL];     // exact (residual)
__device__ float g_h3t [T_LEN * DMODEL];     // rounded (GEMM A)
__device__ float g_gu  [T_LEN * GU_N];
__device__ float g_gb  [T_LEN * FF];         // silu(g)*u, rounded
// transposed + tf32-rounded weights (row n holds column n of W, K-contig)
__device__ float g_wqkvT[QKV_N  * DMODEL];
__device__ float g_woT  [DMODEL * DMODEL];
__device__ float g_wguT [GU_N   * DMODEL];
__device__ float g_wdT  [DMODEL * FF];

// ---------------------------------------------------------------------------
// helpers
// ---------------------------------------------------------------------------
__device__ __forceinline__ uint32_t smem_u32(const void* p) {
    uint32_t a;
    asm("{ .reg .u64 t; cvta.to.shared.u64 t, %1; cvt.u32.u64 %0, t; }" : "=r"(a) : "l"(p));
    return a;
}
__device__ __forceinline__ float to_tf32(float x) {
    asm("cvt.rna.tf32.f32 %0, %1;" : "=f"(x) : "f"(x));
    return x;
}
#define CP16(sm_addr, gptr) \
    asm volatile("cp.async.cg.shared.global [%0], [%1], 16;" :: "r"(sm_addr), "l"(gptr))
#define CP_COMMIT() asm volatile("cp.async.commit_group;")
#define CP_WAIT1()  asm volatile("cp.async.wait_group 1;")

__device__ __forceinline__ void mma_tf32(float* c, const uint32_t* a, const uint32_t* b) {
    asm volatile("mma.sync.aligned.m16n8k8.row.col.f32.tf32.tf32.f32 "
                 "{%0,%1,%2,%3}, {%4,%5,%6,%7}, {%8,%9}, {%0,%1,%2,%3};"
                 : "+f"(c[0]), "+f"(c[1]), "+f"(c[2]), "+f"(c[3])
                 : "r"(a[0]), "r"(a[1]), "r"(a[2]), "r"(a[3]), "r"(b[0]), "r"(b[1]));
}

// ---------------------------------------------------------------------------
// Weight transpose + tf32 round: W[K,N] -> WT[N,K] (WT ptr may be offset)
// ---------------------------------------------------------------------------
__global__ __launch_bounds__(256) void transpose_tf32_k(const float* __restrict__ W,
                                                        float* __restrict__ WT,
                                                        int K, int N)
{
    __shared__ float t[32][33];
    int n0 = blockIdx.x * 32, k0 = blockIdx.y * 32;
    int tx = threadIdx.x, ty = threadIdx.y;
    #pragma unroll
    for (int i = 0; i < 32; i += 8)
        t[ty + i][tx] = W[(size_t)(k0 + ty + i) * N + n0 + tx];
    __syncthreads();
    #pragma unroll
    for (int i = 0; i < 32; i += 8)
        WT[(size_t)(n0 + ty + i) * K + k0 + tx] = to_tf32(t[tx][ty + i]);
}

// ---------------------------------------------------------------------------
// tf32 tensor-core GEMM: C[M,N] = A[M,K] @ WT[N,K]^T (+add0 +add1)
// CTA 128x256, BK=16, 3-stage cp.async, 8 warps x (64x64), 256 threads.
// A and WT must already be tf32-rounded.
// ---------------------------------------------------------------------------
#define ASTRIDE 20                 // floats per smem row (16 + 4 pad)
#define A_BYTES (128 * ASTRIDE * 4)       // 10240
#define STG_B   ((128 + 256) * ASTRIDE * 4)  // 30720 per stage
#define GSM_TOTAL (3 * STG_B)             // 92160

__global__ __launch_bounds__(256, 1) void tgemm_k(const float* __restrict__ A,
                                                  const float* __restrict__ WT,
                                                  float* __restrict__ C,
                                                  int M, int N, int K,
                                                  const float* __restrict__ add0,
                                                  const float* __restrict__ add1)
{
    extern __shared__ char sm[];
    const uint32_t smb = smem_u32(sm);
    const int tid = threadIdx.x;
    const int wid = tid >> 5, lane = tid & 31;
    const int warp_m = wid & 1;        // 0..1 -> 64-row half
    const int warp_n = wid >> 1;       // 0..3 -> 64-col quarter
    const int brow = blockIdx.y * 128;
    const int bcol = blockIdx.x * 256;

    // global load pointers (per thread)
    const float* aG = A  + (size_t)(brow + (tid >> 1)) * K + (tid & 1) * 8;
    const float* bG = WT + (size_t)(bcol + tid) * K;
    const uint32_t sA0 = smb + (tid >> 1) * (ASTRIDE * 4) + (tid & 1) * 32;
    const uint32_t sB0 = smb + A_BYTES + tid * (ASTRIDE * 4);

    float c[4][8][4];
    #pragma unroll
    for (int mi = 0; mi < 4; mi++)
        #pragma unroll
        for (int ni = 0; ni < 8; ni++)
            #pragma unroll
            for (int j = 0; j < 4; j++) c[mi][ni][j] = 0.f;

    const int nk = K >> 4;

    // prologue: stages 0, 1
    #pragma unroll
    for (int p = 0; p < 2; p++) {
        const float* a0 = aG + p * 16;
        const float* b0 = bG + p * 16;
        uint32_t sa = sA0 + p * STG_B;
        uint32_t sb = sB0 + p * STG_B;
        CP16(sa, a0); CP16(sa + 16, a0 + 4);
        CP16(sb, b0); CP16(sb + 16, b0 + 4); CP16(sb + 32, b0 + 8); CP16(sb + 48, b0 + 12);
        CP_COMMIT();
    }

    const int r1 = lane >> 2, cq = lane & 3;

    for (int kt = 0; kt < nk; kt++) {
        CP_WAIT1();
        __syncthreads();

        // issue stage kt+2
        if (kt + 2 < nk) {
            int st = (kt + 2) % 3;
            const float* a0 = aG + (size_t)(kt + 2) * 16;
            const float* b0 = bG + (size_t)(kt + 2) * 16;
            uint32_t sa = sA0 + st * STG_B;
            uint32_t sb = sB0 + st * STG_B;
            CP16(sa, a0); CP16(sa + 16, a0 + 4);
            CP16(sb, b0); CP16(sb + 16, b0 + 4); CP16(sb + 32, b0 + 8); CP16(sb + 48, b0 + 12);
        }
        CP_COMMIT();

        // compute stage kt%3
        const float* As = (const float*)(sm + (kt % 3) * STG_B);
        const float* Bs = As + A_BYTES / 4;
        const float* abase = As + (warp_m * 64 + r1) * ASTRIDE + cq;
        const float* bbase = Bs + (warp_n * 64 + r1) * ASTRIDE + cq;

        #pragma unroll
        for (int kk = 0; kk < 2; kk++) {
            uint32_t a[4][4], b[8][2];
            #pragma unroll
            for (int mi = 0; mi < 4; mi++) {
                const float* ap = abase + mi * 16 * ASTRIDE + kk * 8;
                a[mi][0] = __float_as_uint(ap[0]);
                a[mi][1] = __float_as_uint(ap[8 * ASTRIDE]);
                a[mi][2] = __float_as_uint(ap[4]);
                a[mi][3] = __float_as_uint(ap[8 * ASTRIDE + 4]);
            }
            #pragma unroll
            for (int ni = 0; ni < 8; ni++) {
                const float* bp = bbase + ni * 8 * ASTRIDE + kk * 8;
                b[ni][0] = __float_as_uint(bp[0]);
                b[ni][1] = __float_as_uint(bp[4]);
            }
            #pragma unroll
            for (int mi = 0; mi < 4; mi++)
                #pragma unroll
                for (int ni = 0; ni < 8; ni++)
                    mma_tf32(c[mi][ni], a[mi], b[ni]);
        }
    }

    // epilogue
    #pragma unroll
    for (int mi = 0; mi < 4; mi++) {
        int row0 = brow + warp_m * 64 + mi * 16 + r1;
        #pragma unroll
        for (int part = 0; part < 2; part++) {
            int r = row0 + part * 8;
            size_t rowbase = (size_t)r * N;
            #pragma unroll
            for (int ni = 0; ni < 8; ni++) {
                int col = bcol + warp_n * 64 + ni * 8 + cq * 2;
                float2 v = make_float2(c[mi][ni][part * 2], c[mi][ni][part * 2 + 1]);
                if (add0) { const float2 a2 = *(const float2*)&add0[rowbase + col];
                            v.x += a2.x; v.y += a2.y; }
                if (add1) { const float2 a2 = *(const float2*)&add1[rowbase + col];
                            v.x += a2.x; v.y += a2.y; }
                *(float2*)&C[rowbase + col] = v;
            }
        }
    }
}

// ---------------------------------------------------------------------------
// RMSNorm: out exact, outT tf32-rounded (nullable)
// ---------------------------------------------------------------------------
__global__ __launch_bounds__(256) void rmsnorm_k(const float* __restrict__ x,
                                                 const float* __restrict__ g,
                                                 float* __restrict__ out,
                                                 float* __restrict__ outT)
{
    int row = blockIdx.x;
    int tid = threadIdx.x;
    const float4* xr4 = (const float4*)(x + (size_t)row * DMODEL);
    const float4* g4  = (const float4*)g;

    float4 a = xr4[tid];
    float4 b = xr4[tid + 256];
    float s = a.x*a.x + a.y*a.y + a.z*a.z + a.w*a.w
            + b.x*b.x + b.y*b.y + b.z*b.z + b.w*b.w;
    #pragma unroll
    for (int off = 16; off > 0; off >>= 1) s += __shfl_xor_sync(0xffffffffu, s, off);

    __shared__ float red[8];
    __shared__ float inv_s;
    int wid = tid >> 5, lane = tid & 31;
    if (lane == 0) red[wid] = s;
    __syncthreads();
    if (tid == 0) {
        float t = 0.f;
        #pragma unroll
        for (int w = 0; w < 8; w++) t += red[w];
        inv_s = rsqrtf(t / (float)DMODEL + 1e-5f);
    }
    __syncthreads();
    float inv = inv_s;

    float4 ga = g4[tid], gb = g4[tid + 256];
    float4 ra, rb;
    ra.x = a.x*ga.x*inv; ra.y = a.y*ga.y*inv; ra.z = a.z*ga.z*inv; ra.w = a.w*ga.w*inv;
    rb.x = b.x*gb.x*inv; rb.y = b.y*gb.y*inv; rb.z = b.z*gb.z*inv; rb.w = b.w*gb.w*inv;
    ((float4*)(out + (size_t)row * DMODEL))[tid] = ra;
    ((float4*)(out + (size_t)row * DMODEL))[tid + 256] = rb;
    if (outT) {
        float4 ta = make_float4(to_tf32(ra.x), to_tf32(ra.y), to_tf32(ra.z), to_tf32(ra.w));
        float4 tb = make_float4(to_tf32(rb.x), to_tf32(rb.y), to_tf32(rb.z), to_tf32(rb.w));
        ((float4*)(outT + (size_t)row * DMODEL))[tid] = ta;
        ((float4*)(outT + (size_t)row * DMODEL))[tid + 256] = tb;
    }
}

// ---------------------------------------------------------------------------
// RoPE on fused qkv buffer [T, 3072]: q cols 0..2047, k cols 2048..2559
// ---------------------------------------------------------------------------
__global__ __launch_bounds__(256) void rope_k(float* __restrict__ qkv)
{
    __shared__ float cs[32], sn[32];
    int t = blockIdx.x;
    if (threadIdx.x < 32) {
        int d = threadIdx.x;
        double freq = exp((double)(-2.0 * d / 64.0) * 9.210340371976184);
        double ang  = freq * (double)t;
        double si, co;
        sincos(ang, &si, &co);
        cs[d] = (float)co;
        sn[d] = (float)si;
    }
    __syncthreads();

    const int NPAIR_Q = NHEAD * (HD / 2);   // 1024
    const int NPAIR_K = NKV  * (HD / 2);    // 256
    float* base = qkv + (size_t)t * QKV_N;
    for (int p = threadIdx.x; p < NPAIR_Q + NPAIR_K; p += blockDim.x) {
        float* ptr;
        int d;
        if (p < NPAIR_Q) {
            int head = p >> 5; d = p & 31;
            ptr = base + head * HD + 2 * d;
        } else {
            int pk = p - NPAIR_Q;
            int head = pk >> 5; d = pk & 31;
            ptr = base + DMODEL + head * HD + 2 * d;
        }
        float x1 = ptr[0], x2 = ptr[1];
        float c = cs[d], s = sn[d];
        ptr[0] = x1 * c - x2 * s;
        ptr[1] = x2 * c + x1 * s;
    }
}

// ---------------------------------------------------------------------------
// Flash attention on fused qkv (strides 3072); output tf32-rounded [T,2048]
// ---------------------------------------------------------------------------
__global__ __launch_bounds__(64) void attn_k(const float* __restrict__ QKV,
                                             float* __restrict__ O)
{
    __shared__ float k_s[64][64];
    __shared__ float v_s[64][64];
    __shared__ float s_s[64][64];

    int tid = threadIdx.x;
    int qt  = blockIdx.x;
    int h   = blockIdx.y;
    int kvh = h >> 2;
    int r   = qt * 64 + tid;

    const float* Q = QKV;
    const float* K = QKV + DMODEL;
    const float* V = QKV + DMODEL + 512;

    float qreg[64];
    {
        const float4* qp = (const float4*)(Q + (size_t)r * QKV_N + h * HD);
        #pragma unroll
        for (int i = 0; i < 16; i++) {
            float4 t4 = qp[i];
            qreg[4*i+0] = t4.x; qreg[4*i+1] = t4.y;
            qreg[4*i+2] = t4.z; qreg[4*i+3] = t4.w;
        }
    }

    float o[64];
    #pragma unroll
    for (int d = 0; d < 64; d++) o[d] = 0.f;
    float m = -3e38f, l = 0.f;

    for (int jt = 0; jt <= qt; jt++) {
        const float* kp = K + (size_t)(jt * 64) * QKV_N + kvh * HD;
        const float* vp = V + (size_t)(jt * 64) * QKV_N + kvh * HD;
        #pragma unroll 4
        for (int it = 0; it < 64; it++) {
            k_s[it][tid] = kp[(size_t)it * QKV_N + tid];
            v_s[it][tid] = vp[(size_t)it * QKV_N + tid];
        }
        __syncthreads();

        bool dtile = (jt == qt);
        float mx = m;
        #pragma unroll 1
        for (int c = 0; c < 64; c++) {
            float acc = 0.f;
            #pragma unroll
            for (int kk = 0; kk < 64; kk++) acc += qreg[kk] * k_s[c][kk];
            acc *= 0.125f;
            if (dtile && (jt * 64 + c) > r) acc = -1e30f;
            s_s[c][tid] = acc;
            mx = fmaxf(mx, acc);
        }

        float corr = __expf(m - mx);
        m = mx;
        l *= corr;
        #pragma unroll
        for (int d = 0; d < 64; d++) o[d] *= corr;

        #pragma unroll 1
        for (int c = 0; c < 64; c++) {
            float p = __expf(s_s[c][tid] - mx);
            l += p;
            #pragma unroll
            for (int d = 0; d < 64; d++) o[d] += p * v_s[c][d];
        }
        __syncthreads();
    }

    float inv = 1.0f / l;
    float4* op = (float4*)(O + (size_t)r * DMODEL + h * HD);
    #pragma unroll
    for (int i = 0; i < 16; i++)
        op[i] = make_float4(to_tf32(o[4*i+0]*inv), to_tf32(o[4*i+1]*inv),
                            to_tf32(o[4*i+2]*inv), to_tf32(o[4*i+3]*inv));
}

// ---------------------------------------------------------------------------
// silu(gate)*up from fused gu buffer -> gb (tf32-rounded)
// ---------------------------------------------------------------------------
__global__ __launch_bounds__(256) void silu_mul_k(const float* __restrict__ gu,
                                                  float* __restrict__ gb)
{
    int i = blockIdx.x * blockDim.x + threadIdx.x;   // over T*FF/4
    int row  = i >> 11;                              // FF/4 = 2048 float4 per row
    int col4 = i & 2047;
    const float4 a = ((const float4*)(gu + (size_t)row * GU_N))[col4];
    const float4 b = ((const float4*)(gu + (size_t)row * GU_N + FF))[col4];
    float4 r;
    r.x = to_tf32(a.x / (1.f + __expf(-a.x)) * b.x);
    r.y = to_tf32(a.y / (1.f + __expf(-a.y)) * b.y);
    r.z = to_tf32(a.z / (1.f + __expf(-a.z)) * b.z);
    r.w = to_tf32(a.w / (1.f + __expf(-a.w)) * b.w);
    ((float4*)(gb + (size_t)row * FF))[col4] = r;
}

// ---------------------------------------------------------------------------
// kernel_launch
// ---------------------------------------------------------------------------
extern "C" void kernel_launch(void* const* d_in, const int* in_sizes, int n_in,
                              void* d_out, int out_size)
{
    (void)in_sizes; (void)n_in; (void)out_size;
    const float* x  = (const float*)d_in[0];
    const float* g1 = (const float*)d_in[1];
    const float* wq = (const float*)d_in[2];
    const float* wk = (const float*)d_in[3];
    const float* wv = (const float*)d_in[4];
    const float* wo = (const float*)d_in[5];
    const float* g2 = (const float*)d_in[6];
    const float* wg = (const float*)d_in[7];
    const float* wu = (const float*)d_in[8];
    const float* wd = (const float*)d_in[9];
    float* out = (float*)d_out;

    float *xn, *xnt, *qkv, *att, *h2, *h3, *h3t, *gu, *gb;
    float *wqkvT, *woT, *wguT, *wdT;
    cudaGetSymbolAddress((void**)&xn,    g_xn);
    cudaGetSymbolAddress((void**)&xnt,   g_xnt);
    cudaGetSymbolAddress((void**)&qkv,   g_qkv);
    cudaGetSymbolAddress((void**)&att,   g_att);
    cudaGetSymbolAddress((void**)&h2,    g_h2);
    cudaGetSymbolAddress((void**)&h3,    g_h3);
    cudaGetSymbolAddress((void**)&h3t,   g_h3t);
    cudaGetSymbolAddress((void**)&gu,    g_gu);
    cudaGetSymbolAddress((void**)&gb,    g_gb);
    cudaGetSymbolAddress((void**)&wqkvT, g_wqkvT);
    cudaGetSymbolAddress((void**)&woT,   g_woT);
    cudaGetSymbolAddress((void**)&wguT,  g_wguT);
    cudaGetSymbolAddress((void**)&wdT,   g_wdT);

    cudaFuncSetAttribute(tgemm_k, cudaFuncAttributeMaxDynamicSharedMemorySize, GSM_TOTAL);

    dim3 tb(32, 8);
    // fused transposed weights
    transpose_tf32_k<<<dim3(DMODEL/32, DMODEL/32), tb>>>(wq, wqkvT,               DMODEL, DMODEL);
    transpose_tf32_k<<<dim3(512/32,    DMODEL/32), tb>>>(wk, wqkvT + (size_t)2048*DMODEL, DMODEL, 512);
    transpose_tf32_k<<<dim3(512/32,    DMODEL/32), tb>>>(wv, wqkvT + (size_t)2560*DMODEL, DMODEL, 512);
    transpose_tf32_k<<<dim3(DMODEL/32, DMODEL/32), tb>>>(wo, woT,                 DMODEL, DMODEL);
    transpose_tf32_k<<<dim3(FF/32,     DMODEL/32), tb>>>(wg, wguT,                DMODEL, FF);
    transpose_tf32_k<<<dim3(FF/32,     DMODEL/32), tb>>>(wu, wguT + (size_t)FF*DMODEL,   DMODEL, FF);
    transpose_tf32_k<<<dim3(DMODEL/32, FF/32),     tb>>>(wd, wdT,                 FF, DMODEL);

    // h1 = rmsnorm(x, g1): exact + rounded
    rmsnorm_k<<<T_LEN, 256>>>(x, g1, xn, xnt);

    // qkv = h1t @ [wq|wk|wv]
    tgemm_k<<<dim3(QKV_N/256, T_LEN/128), 256, GSM_TOTAL>>>(xnt, wqkvT, qkv,
                                                            T_LEN, QKV_N, DMODEL, nullptr, nullptr);
    rope_k<<<T_LEN, 256>>>(qkv);
    attn_k<<<dim3(T_LEN/64, NHEAD), 64>>>(qkv, att);

    // h2 = h1 + att @ wo
    tgemm_k<<<dim3(DMODEL/256, T_LEN/128), 256, GSM_TOTAL>>>(att, woT, h2,
                                                             T_LEN, DMODEL, DMODEL, xn, nullptr);

    // h3 = rmsnorm(h2, g2): exact + rounded
    rmsnorm_k<<<T_LEN, 256>>>(h2, g2, h3, h3t);

    // gu = h3t @ [wg|wu]
    tgemm_k<<<dim3(GU_N/256, T_LEN/128), 256, GSM_TOTAL>>>(h3t, wguT, gu,
                                                           T_LEN, GU_N, DMODEL, nullptr, nullptr);

    // gb = tf32(silu(gate) * up)
    int n4 = T_LEN * FF / 4;
    silu_mul_k<<<n4 / 256, 256>>>(gu, gb);

    // out = gb @ wd + h3 + x
    tgemm_k<<<dim3(DMODEL/256, T_LEN/128), 256, GSM_TOTAL>>>(gb, wdT, out,
                                                             T_LEN, DMODEL, FF, h3, x);
}

// round 5
// speedup vs baseline: 3.2169x; 1.3351x over previous
#include <cuda_runtime.h>
#include <cstdint>
#include <cstddef>

// ---------------------------------------------------------------------------
// LlamaDecoderLayer fp32. GEMMs + attention via portable mma.sync tf32.
// T=2048, D=2048, NH=32, NKV=8, HD=64, FF=8192.
// ---------------------------------------------------------------------------

#define T_LEN 2048
#define DMODEL 2048
#define NHEAD 32
#define NKV 8
#define HD 64
#define FF 8192
#define QKV_N 3072          // 2048 q + 512 k + 512 v
#define GU_N  16384         // gate 8192 + up 8192

// ---- scratch -------------------------------------------------------------
__device__ float g_xn  [T_LEN * DMODEL];     // h1 exact (residual)
__device__ float g_xnt [T_LEN * DMODEL];     // h1 tf32-rounded (GEMM A)
__device__ float g_qkv [T_LEN * QKV_N];
__device__ float g_att [T_LEN * DMODEL];     // attention out, tf32-rounded
__device__ float g_h2  [T_LEN * DMODEL];
__device__ float g_h3  [T_LEN * DMODEL];     // exact (residual)
__device__ float g_h3t [T_LEN * DMODEL];     // rounded (GEMM A)
__device__ float g_gu  [T_LEN * GU_N];
__device__ float g_gb  [T_LEN * FF];         // silu(g)*u, rounded
// transposed + tf32-rounded weights
__device__ float g_wqkvT[QKV_N  * DMODEL];
__device__ float g_woT  [DMODEL * DMODEL];
__device__ float g_wguT [GU_N   * DMODEL];
__device__ float g_wdT  [DMODEL * FF];

// ---------------------------------------------------------------------------
// helpers
// ---------------------------------------------------------------------------
__device__ __forceinline__ uint32_t smem_u32(const void* p) {
    uint32_t a;
    asm("{ .reg .u64 t; cvta.to.shared.u64 t, %1; cvt.u32.u64 %0, t; }" : "=r"(a) : "l"(p));
    return a;
}
__device__ __forceinline__ float to_tf32(float x) {
    asm("cvt.rna.tf32.f32 %0, %1;" : "=f"(x) : "f"(x));
    return x;
}
#define CP16(sm_addr, gptr) \
    asm volatile("cp.async.cg.shared.global [%0], [%1], 16;" :: "r"(sm_addr), "l"(gptr))
#define CP_COMMIT() asm volatile("cp.async.commit_group;")
#define CP_WAIT1()  asm volatile("cp.async.wait_group 1;")

__device__ __forceinline__ void mma_tf32(float* c, const uint32_t* a, const uint32_t* b) {
    asm volatile("mma.sync.aligned.m16n8k8.row.col.f32.tf32.tf32.f32 "
                 "{%0,%1,%2,%3}, {%4,%5,%6,%7}, {%8,%9}, {%0,%1,%2,%3};"
                 : "+f"(c[0]), "+f"(c[1]), "+f"(c[2]), "+f"(c[3])
                 : "r"(a[0]), "r"(a[1]), "r"(a[2]), "r"(a[3]), "r"(b[0]), "r"(b[1]));
}
__device__ __forceinline__ void mma_f(float* c, const float* a, const float* b) {
    asm volatile("mma.sync.aligned.m16n8k8.row.col.f32.tf32.tf32.f32 "
                 "{%0,%1,%2,%3}, {%4,%5,%6,%7}, {%8,%9}, {%0,%1,%2,%3};"
                 : "+f"(c[0]), "+f"(c[1]), "+f"(c[2]), "+f"(c[3])
                 : "r"(__float_as_uint(a[0])), "r"(__float_as_uint(a[1])),
                   "r"(__float_as_uint(a[2])), "r"(__float_as_uint(a[3])),
                   "r"(__float_as_uint(b[0])), "r"(__float_as_uint(b[1])));
}

// ---------------------------------------------------------------------------
// Weight transpose + tf32 round: W[K,N] -> WT[N,K]
// ---------------------------------------------------------------------------
__global__ __launch_bounds__(256) void transpose_tf32_k(const float* __restrict__ W,
                                                        float* __restrict__ WT,
                                                        int K, int N)
{
    __shared__ float t[32][33];
    int n0 = blockIdx.x * 32, k0 = blockIdx.y * 32;
    int tx = threadIdx.x, ty = threadIdx.y;
    #pragma unroll
    for (int i = 0; i < 32; i += 8)
        t[ty + i][tx] = W[(size_t)(k0 + ty + i) * N + n0 + tx];
    __syncthreads();
    #pragma unroll
    for (int i = 0; i < 32; i += 8)
        WT[(size_t)(n0 + ty + i) * K + k0 + tx] = to_tf32(t[tx][ty + i]);
}

// ---------------------------------------------------------------------------
// tf32 tensor-core GEMM: C[M,N] = A[M,K] @ WT[N,K]^T (+add0 +add1)
// CTA 128x256, BK=16, 3-stage cp.async, 8 warps x (64x64).
// ---------------------------------------------------------------------------
#define ASTRIDE 20
#define A_BYTES (128 * ASTRIDE * 4)
#define STG_B   ((128 + 256) * ASTRIDE * 4)
#define GSM_TOTAL (3 * STG_B)

__global__ __launch_bounds__(256, 1) void tgemm_k(const float* __restrict__ A,
                                                  const float* __restrict__ WT,
                                                  float* __restrict__ C,
                                                  int M, int N, int K,
                                                  const float* __restrict__ add0,
                                                  const float* __restrict__ add1)
{
    extern __shared__ char sm[];
    const uint32_t smb = smem_u32(sm);
    const int tid = threadIdx.x;
    const int wid = tid >> 5, lane = tid & 31;
    const int warp_m = wid & 1;
    const int warp_n = wid >> 1;
    const int brow = blockIdx.y * 128;
    const int bcol = blockIdx.x * 256;

    const float* aG = A  + (size_t)(brow + (tid >> 1)) * K + (tid & 1) * 8;
    const float* bG = WT + (size_t)(bcol + tid) * K;
    const uint32_t sA0 = smb + (tid >> 1) * (ASTRIDE * 4) + (tid & 1) * 32;
    const uint32_t sB0 = smb + A_BYTES + tid * (ASTRIDE * 4);

    float c[4][8][4];
    #pragma unroll
    for (int mi = 0; mi < 4; mi++)
        #pragma unroll
        for (int ni = 0; ni < 8; ni++)
            #pragma unroll
            for (int j = 0; j < 4; j++) c[mi][ni][j] = 0.f;

    const int nk = K >> 4;

    #pragma unroll
    for (int p = 0; p < 2; p++) {
        const float* a0 = aG + p * 16;
        const float* b0 = bG + p * 16;
        uint32_t sa = sA0 + p * STG_B;
        uint32_t sb = sB0 + p * STG_B;
        CP16(sa, a0); CP16(sa + 16, a0 + 4);
        CP16(sb, b0); CP16(sb + 16, b0 + 4); CP16(sb + 32, b0 + 8); CP16(sb + 48, b0 + 12);
        CP_COMMIT();
    }

    const int r1 = lane >> 2, cq = lane & 3;

    for (int kt = 0; kt < nk; kt++) {
        CP_WAIT1();
        __syncthreads();

        if (kt + 2 < nk) {
            int st = (kt + 2) % 3;
            const float* a0 = aG + (size_t)(kt + 2) * 16;
            const float* b0 = bG + (size_t)(kt + 2) * 16;
            uint32_t sa = sA0 + st * STG_B;
            uint32_t sb = sB0 + st * STG_B;
            CP16(sa, a0); CP16(sa + 16, a0 + 4);
            CP16(sb, b0); CP16(sb + 16, b0 + 4); CP16(sb + 32, b0 + 8); CP16(sb + 48, b0 + 12);
        }
        CP_COMMIT();

        const float* As = (const float*)(sm + (kt % 3) * STG_B);
        const float* Bs = As + A_BYTES / 4;
        const float* abase = As + (warp_m * 64 + r1) * ASTRIDE + cq;
        const float* bbase = Bs + (warp_n * 64 + r1) * ASTRIDE + cq;

        #pragma unroll
        for (int kk = 0; kk < 2; kk++) {
            uint32_t a[4][4], b[8][2];
            #pragma unroll
            for (int mi = 0; mi < 4; mi++) {
                const float* ap = abase + mi * 16 * ASTRIDE + kk * 8;
                a[mi][0] = __float_as_uint(ap[0]);
                a[mi][1] = __float_as_uint(ap[8 * ASTRIDE]);
                a[mi][2] = __float_as_uint(ap[4]);
                a[mi][3] = __float_as_uint(ap[8 * ASTRIDE + 4]);
            }
            #pragma unroll
            for (int ni = 0; ni < 8; ni++) {
                const float* bp = bbase + ni * 8 * ASTRIDE + kk * 8;
                b[ni][0] = __float_as_uint(bp[0]);
                b[ni][1] = __float_as_uint(bp[4]);
            }
            #pragma unroll
            for (int mi = 0; mi < 4; mi++)
                #pragma unroll
                for (int ni = 0; ni < 8; ni++)
                    mma_tf32(c[mi][ni], a[mi], b[ni]);
        }
    }

    #pragma unroll
    for (int mi = 0; mi < 4; mi++) {
        int row0 = brow + warp_m * 64 + mi * 16 + r1;
        #pragma unroll
        for (int part = 0; part < 2; part++) {
            int r = row0 + part * 8;
            size_t rowbase = (size_t)r * N;
            #pragma unroll
            for (int ni = 0; ni < 8; ni++) {
                int col = bcol + warp_n * 64 + ni * 8 + cq * 2;
                float2 v = make_float2(c[mi][ni][part * 2], c[mi][ni][part * 2 + 1]);
                if (add0) { const float2 a2 = *(const float2*)&add0[rowbase + col];
                            v.x += a2.x; v.y += a2.y; }
                if (add1) { const float2 a2 = *(const float2*)&add1[rowbase + col];
                            v.x += a2.x; v.y += a2.y; }
                *(float2*)&C[rowbase + col] = v;
            }
        }
    }
}

// ---------------------------------------------------------------------------
// Tensor-core flash attention (causal GQA). Block = 64 q rows x 1 head,
// 4 warps, each warp 16 q rows. All mma tf32 m16n8k8.
// smem floats: qsm 64x68 | ksm 64x68 | vsm 64x72 | psm 4x16x68
// ---------------------------------------------------------------------------
#define ATT_SMEM_FLOATS (4352 + 4352 + 4608 + 4352)
#define ATT_SMEM_BYTES  (ATT_SMEM_FLOATS * 4)

__global__ __launch_bounds__(128) void attn_tc_k(const float* __restrict__ QKV,
                                                 float* __restrict__ Oa)
{
    extern __shared__ float s[];
    float* qsm = s;                  // [64][68]
    float* ksm = s + 4352;           // [64][68]
    float* vsm = s + 8704;           // [64][72]
    float* psm = s + 13312;          // [4][16][68]

    const int tid = threadIdx.x;
    const int w = tid >> 5, lane = tid & 31;
    const int r1 = lane >> 2, cq = lane & 3;
    const int qt = blockIdx.x, h = blockIdx.y;
    const int kvh = h >> 2;

    // ---- load Q tile (rounded) ----
    {
        const float* qb = QKV + (size_t)(qt * 64) * QKV_N + h * HD;
        for (int t = tid; t < 1024; t += 128) {
            int i = t >> 4, d4 = (t & 15) * 4;
            float4 v4 = *(const float4*)(qb + (size_t)i * QKV_N + d4);
            v4.x = to_tf32(v4.x); v4.y = to_tf32(v4.y);
            v4.z = to_tf32(v4.z); v4.w = to_tf32(v4.w);
            *(float4*)(qsm + i * 68 + d4) = v4;
        }
    }
    __syncthreads();

    // ---- Q fragments (row-major A: rows w*16+r1, w*16+r1+8) ----
    float qf[8][4];
    {
        const float* qb = qsm + (w * 16 + r1) * 68 + cq;
        #pragma unroll
        for (int ks = 0; ks < 8; ks++) {
            qf[ks][0] = qb[ks * 8];
            qf[ks][1] = qb[8 * 68 + ks * 8];
            qf[ks][2] = qb[ks * 8 + 4];
            qf[ks][3] = qb[8 * 68 + ks * 8 + 4];
        }
    }

    float oA[8][4];
    #pragma unroll
    for (int nt = 0; nt < 8; nt++)
        #pragma unroll
        for (int j = 0; j < 4; j++) oA[nt][j] = 0.f;
    float m0 = -1e30f, m1 = -1e30f, l0 = 0.f, l1 = 0.f;

    float* pb = psm + w * 16 * 68;

    for (int jt = 0; jt <= qt; jt++) {
        __syncthreads();   // previous iteration's vsm reads complete
        {
            const float* kb = QKV + (size_t)(jt * 64) * QKV_N + DMODEL + kvh * HD;
            const float* vb = kb + 512;
            for (int t = tid; t < 1024; t += 128) {
                int i = t >> 4, d4 = (t & 15) * 4;
                float4 k4 = *(const float4*)(kb + (size_t)i * QKV_N + d4);
                k4.x = to_tf32(k4.x); k4.y = to_tf32(k4.y);
                k4.z = to_tf32(k4.z); k4.w = to_tf32(k4.w);
                *(float4*)(ksm + i * 68 + d4) = k4;
                float4 v4 = *(const float4*)(vb + (size_t)i * QKV_N + d4);
                v4.x = to_tf32(v4.x); v4.y = to_tf32(v4.y);
                v4.z = to_tf32(v4.z); v4.w = to_tf32(v4.w);
                *(float4*)(vsm + i * 72 + d4) = v4;
            }
        }
        __syncthreads();

        // ---- S = Q @ K^T (scaled) ----
        float sA[8][4];
        #pragma unroll
        for (int nt = 0; nt < 8; nt++) {
            float acc[4] = {0.f, 0.f, 0.f, 0.f};
            const float* kbp = ksm + (nt * 8 + r1) * 68 + cq;
            #pragma unroll
            for (int ks = 0; ks < 8; ks++) {
                float bf[2] = { kbp[ks * 8], kbp[ks * 8 + 4] };
                mma_f(acc, qf[ks], bf);
            }
            sA[nt][0] = acc[0]; sA[nt][1] = acc[1];
            sA[nt][2] = acc[2]; sA[nt][3] = acc[3];
        }

        // ---- scale + causal mask + row max ----
        float mn0 = m0, mn1 = m1;
        const int row0 = w * 16 + r1, row1 = row0 + 8;
        #pragma unroll
        for (int nt = 0; nt < 8; nt++) {
            #pragma unroll
            for (int j = 0; j < 4; j++) sA[nt][j] *= 0.125f;
            if (jt == qt) {
                int colb = nt * 8 + 2 * cq;
                if (colb     > row0) sA[nt][0] = -1e30f;
                if (colb + 1 > row0) sA[nt][1] = -1e30f;
                if (colb     > row1) sA[nt][2] = -1e30f;
                if (colb + 1 > row1) sA[nt][3] = -1e30f;
            }
            mn0 = fmaxf(mn0, fmaxf(sA[nt][0], sA[nt][1]));
            mn1 = fmaxf(mn1, fmaxf(sA[nt][2], sA[nt][3]));
        }
        mn0 = fmaxf(mn0, __shfl_xor_sync(0xffffffffu, mn0, 1));
        mn0 = fmaxf(mn0, __shfl_xor_sync(0xffffffffu, mn0, 2));
        mn1 = fmaxf(mn1, __shfl_xor_sync(0xffffffffu, mn1, 1));
        mn1 = fmaxf(mn1, __shfl_xor_sync(0xffffffffu, mn1, 2));

        float c0 = __expf(m0 - mn0), c1 = __expf(m1 - mn1);
        m0 = mn0; m1 = mn1;

        // ---- P = exp(S - m), rounded; write to psm; partial row sums ----
        float ls0 = 0.f, ls1 = 0.f;
        #pragma unroll
        for (int nt = 0; nt < 8; nt++) {
            float p0 = to_tf32(__expf(sA[nt][0] - mn0));
            float p1 = to_tf32(__expf(sA[nt][1] - mn0));
            float p2 = to_tf32(__expf(sA[nt][2] - mn1));
            float p3 = to_tf32(__expf(sA[nt][3] - mn1));
            ls0 += p0 + p1; ls1 += p2 + p3;
            int cb = nt * 8 + 2 * cq;
            pb[r1 * 68 + cb]       = p0;
            pb[r1 * 68 + cb + 1]   = p1;
            pb[(r1 + 8) * 68 + cb]     = p2;
            pb[(r1 + 8) * 68 + cb + 1] = p3;
        }
        ls0 += __shfl_xor_sync(0xffffffffu, ls0, 1);
        ls0 += __shfl_xor_sync(0xffffffffu, ls0, 2);
        ls1 += __shfl_xor_sync(0xffffffffu, ls1, 1);
        ls1 += __shfl_xor_sync(0xffffffffu, ls1, 2);
        l0 = l0 * c0 + ls0;
        l1 = l1 * c1 + ls1;

        // ---- rescale O ----
        #pragma unroll
        for (int nt = 0; nt < 8; nt++) {
            oA[nt][0] *= c0; oA[nt][1] *= c0;
            oA[nt][2] *= c1; oA[nt][3] *= c1;
        }
        __syncwarp();

        // ---- O += P @ V ----
        #pragma unroll
        for (int ks = 0; ks < 8; ks++) {
            float af[4];
            af[0] = pb[r1 * 68 + ks * 8 + cq];
            af[1] = pb[(r1 + 8) * 68 + ks * 8 + cq];
            af[2] = pb[r1 * 68 + ks * 8 + cq + 4];
            af[3] = pb[(r1 + 8) * 68 + ks * 8 + cq + 4];
            const float* vb0 = vsm + (ks * 8 + cq) * 72 + r1;
            const float* vb1 = vsm + (ks * 8 + cq + 4) * 72 + r1;
            #pragma unroll
            for (int nt = 0; nt < 8; nt++) {
                float bf[2] = { vb0[nt * 8], vb1[nt * 8] };
                mma_f(oA[nt], af, bf);
            }
        }
    }

    // ---- epilogue ----
    float inv0 = 1.f / l0, inv1 = 1.f / l1;
    int gr0 = qt * 64 + w * 16 + r1;
    #pragma unroll
    for (int nt = 0; nt < 8; nt++) {
        int col = h * HD + nt * 8 + 2 * cq;
        float2 v0 = make_float2(to_tf32(oA[nt][0] * inv0), to_tf32(oA[nt][1] * inv0));
        float2 v1 = make_float2(to_tf32(oA[nt][2] * inv1), to_tf32(oA[nt][3] * inv1));
        *(float2*)&Oa[(size_t)gr0 * DMODEL + col] = v0;
        *(float2*)&Oa[(size_t)(gr0 + 8) * DMODEL + col] = v1;
    }
}

// ---------------------------------------------------------------------------
// RMSNorm: out exact, outT tf32-rounded (nullable)
// ---------------------------------------------------------------------------
__global__ __launch_bounds__(256) void rmsnorm_k(const float* __restrict__ x,
                                                 const float* __restrict__ g,
                                                 float* __restrict__ out,
                                                 float* __restrict__ outT)
{
    int row = blockIdx.x;
    int tid = threadIdx.x;
    const float4* xr4 = (const float4*)(x + (size_t)row * DMODEL);
    const float4* g4  = (const float4*)g;

    float4 a = xr4[tid];
    float4 b = xr4[tid + 256];
    float s = a.x*a.x + a.y*a.y + a.z*a.z + a.w*a.w
            + b.x*b.x + b.y*b.y + b.z*b.z + b.w*b.w;
    #pragma unroll
    for (int off = 16; off > 0; off >>= 1) s += __shfl_xor_sync(0xffffffffu, s, off);

    __shared__ float red[8];
    __shared__ float inv_s;
    int wid = tid >> 5, lane = tid & 31;
    if (lane == 0) red[wid] = s;
    __syncthreads();
    if (tid == 0) {
        float t = 0.f;
        #pragma unroll
        for (int w = 0; w < 8; w++) t += red[w];
        inv_s = rsqrtf(t / (float)DMODEL + 1e-5f);
    }
    __syncthreads();
    float inv = inv_s;

    float4 ga = g4[tid], gb = g4[tid + 256];
    float4 ra, rb;
    ra.x = a.x*ga.x*inv; ra.y = a.y*ga.y*inv; ra.z = a.z*ga.z*inv; ra.w = a.w*ga.w*inv;
    rb.x = b.x*gb.x*inv; rb.y = b.y*gb.y*inv; rb.z = b.z*gb.z*inv; rb.w = b.w*gb.w*inv;
    ((float4*)(out + (size_t)row * DMODEL))[tid] = ra;
    ((float4*)(out + (size_t)row * DMODEL))[tid + 256] = rb;
    if (outT) {
        float4 ta = make_float4(to_tf32(ra.x), to_tf32(ra.y), to_tf32(ra.z), to_tf32(ra.w));
        float4 tb = make_float4(to_tf32(rb.x), to_tf32(rb.y), to_tf32(rb.z), to_tf32(rb.w));
        ((float4*)(outT + (size_t)row * DMODEL))[tid] = ta;
        ((float4*)(outT + (size_t)row * DMODEL))[tid + 256] = tb;
    }
}

// ---------------------------------------------------------------------------
// RoPE on fused qkv buffer [T, 3072]
// ---------------------------------------------------------------------------
__global__ __launch_bounds__(256) void rope_k(float* __restrict__ qkv)
{
    __shared__ float cs[32], sn[32];
    int t = blockIdx.x;
    if (threadIdx.x < 32) {
        int d = threadIdx.x;
        double freq = exp((double)(-2.0 * d / 64.0) * 9.210340371976184);
        double ang  = freq * (double)t;
        double si, co;
        sincos(ang, &si, &co);
        cs[d] = (float)co;
        sn[d] = (float)si;
    }
    __syncthreads();

    const int NPAIR_Q = NHEAD * (HD / 2);
    const int NPAIR_K = NKV  * (HD / 2);
    float* base = qkv + (size_t)t * QKV_N;
    for (int p = threadIdx.x; p < NPAIR_Q + NPAIR_K; p += blockDim.x) {
        float* ptr;
        int d;
        if (p < NPAIR_Q) {
            int head = p >> 5; d = p & 31;
            ptr = base + head * HD + 2 * d;
        } else {
            int pk = p - NPAIR_Q;
            int head = pk >> 5; d = pk & 31;
            ptr = base + DMODEL + head * HD + 2 * d;
        }
        float x1 = ptr[0], x2 = ptr[1];
        float c = cs[d], s = sn[d];
        ptr[0] = x1 * c - x2 * s;
        ptr[1] = x2 * c + x1 * s;
    }
}

// ---------------------------------------------------------------------------
// silu(gate)*up from fused gu buffer -> gb (tf32-rounded)
// ---------------------------------------------------------------------------
__global__ __launch_bounds__(256) void silu_mul_k(const float* __restrict__ gu,
                                                  float* __restrict__ gb)
{
    int i = blockIdx.x * blockDim.x + threadIdx.x;
    int row  = i >> 11;
    int col4 = i & 2047;
    const float4 a = ((const float4*)(gu + (size_t)row * GU_N))[col4];
    const float4 b = ((const float4*)(gu + (size_t)row * GU_N + FF))[col4];
    float4 r;
    r.x = to_tf32(a.x / (1.f + __expf(-a.x)) * b.x);
    r.y = to_tf32(a.y / (1.f + __expf(-a.y)) * b.y);
    r.z = to_tf32(a.z / (1.f + __expf(-a.z)) * b.z);
    r.w = to_tf32(a.w / (1.f + __expf(-a.w)) * b.w);
    ((float4*)(gb + (size_t)row * FF))[col4] = r;
}

// ---------------------------------------------------------------------------
// kernel_launch
// ---------------------------------------------------------------------------
extern "C" void kernel_launch(void* const* d_in, const int* in_sizes, int n_in,
                              void* d_out, int out_size)
{
    (void)in_sizes; (void)n_in; (void)out_size;
    const float* x  = (const float*)d_in[0];
    const float* g1 = (const float*)d_in[1];
    const float* wq = (const float*)d_in[2];
    const float* wk = (const float*)d_in[3];
    const float* wv = (const float*)d_in[4];
    const float* wo = (const float*)d_in[5];
    const float* g2 = (const float*)d_in[6];
    const float* wg = (const float*)d_in[7];
    const float* wu = (const float*)d_in[8];
    const float* wd = (const float*)d_in[9];
    float* out = (float*)d_out;

    float *xn, *xnt, *qkv, *att, *h2, *h3, *h3t, *gu, *gb;
    float *wqkvT, *woT, *wguT, *wdT;
    cudaGetSymbolAddress((void**)&xn,    g_xn);
    cudaGetSymbolAddress((void**)&xnt,   g_xnt);
    cudaGetSymbolAddress((void**)&qkv,   g_qkv);
    cudaGetSymbolAddress((void**)&att,   g_att);
    cudaGetSymbolAddress((void**)&h2,    g_h2);
    cudaGetSymbolAddress((void**)&h3,    g_h3);
    cudaGetSymbolAddress((void**)&h3t,   g_h3t);
    cudaGetSymbolAddress((void**)&gu,    g_gu);
    cudaGetSymbolAddress((void**)&gb,    g_gb);
    cudaGetSymbolAddress((void**)&wqkvT, g_wqkvT);
    cudaGetSymbolAddress((void**)&woT,   g_woT);
    cudaGetSymbolAddress((void**)&wguT,  g_wguT);
    cudaGetSymbolAddress((void**)&wdT,   g_wdT);

    cudaFuncSetAttribute(tgemm_k,   cudaFuncAttributeMaxDynamicSharedMemorySize, GSM_TOTAL);
    cudaFuncSetAttribute(attn_tc_k, cudaFuncAttributeMaxDynamicSharedMemorySize, ATT_SMEM_BYTES);

    dim3 tb(32, 8);
    transpose_tf32_k<<<dim3(DMODEL/32, DMODEL/32), tb>>>(wq, wqkvT,               DMODEL, DMODEL);
    transpose_tf32_k<<<dim3(512/32,    DMODEL/32), tb>>>(wk, wqkvT + (size_t)2048*DMODEL, DMODEL, 512);
    transpose_tf32_k<<<dim3(512/32,    DMODEL/32), tb>>>(wv, wqkvT + (size_t)2560*DMODEL, DMODEL, 512);
    transpose_tf32_k<<<dim3(DMODEL/32, DMODEL/32), tb>>>(wo, woT,                 DMODEL, DMODEL);
    transpose_tf32_k<<<dim3(FF/32,     DMODEL/32), tb>>>(wg, wguT,                DMODEL, FF);
    transpose_tf32_k<<<dim3(FF/32,     DMODEL/32), tb>>>(wu, wguT + (size_t)FF*DMODEL,   DMODEL, FF);
    transpose_tf32_k<<<dim3(DMODEL/32, FF/32),     tb>>>(wd, wdT,                 FF, DMODEL);

    rmsnorm_k<<<T_LEN, 256>>>(x, g1, xn, xnt);

    tgemm_k<<<dim3(QKV_N/256, T_LEN/128), 256, GSM_TOTAL>>>(xnt, wqkvT, qkv,
                                                            T_LEN, QKV_N, DMODEL, nullptr, nullptr);
    rope_k<<<T_LEN, 256>>>(qkv);

    attn_tc_k<<<dim3(T_LEN/64, NHEAD), 128, ATT_SMEM_BYTES>>>(qkv, att);

    tgemm_k<<<dim3(DMODEL/256, T_LEN/128), 256, GSM_TOTAL>>>(att, woT, h2,
                                                             T_LEN, DMODEL, DMODEL, xn, nullptr);

    rmsnorm_k<<<T_LEN, 256>>>(h2, g2, h3, h3t);

    tgemm_k<<<dim3(GU_N/256, T_LEN/128), 256, GSM_TOTAL>>>(h3t, wguT, gu,
                                                           T_LEN, GU_N, DMODEL, nullptr, nullptr);

    int n4 = T_LEN * FF / 4;
    silu_mul_k<<<n4 / 256, 256>>>(gu, gb);

    tgemm_k<<<dim3(DMODEL/256, T_LEN/128), 256, GSM_TOTAL>>>(gb, wdT, out,
                                                             T_LEN, DMODEL, FF, h3, x);
}

// round 10
// speedup vs baseline: 4.0103x; 1.2467x over previous
#include <cuda_runtime.h>
#include <cstdint>
#include <cstddef>

// ---------------------------------------------------------------------------
// LlamaDecoderLayer fp32. GEMMs + attention via portable mma.sync tf32.
// B operands stream directly from original W[K,N] (no transpose pass).
// T=2048, D=2048, NH=32, NKV=8, HD=64, FF=8192.
// ---------------------------------------------------------------------------

#define T_LEN 2048
#define DMODEL 2048
#define NHEAD 32
#define NKV 8
#define HD 64
#define FF 8192
#define QKV_N 3072

// ---- scratch -------------------------------------------------------------
__device__ float g_xn  [T_LEN * DMODEL];     // h1 exact (residual)
__device__ float g_xnt [T_LEN * DMODEL];     // h1 tf32-rounded (GEMM A)
__device__ float g_qkv [T_LEN * QKV_N];
__device__ float g_att [T_LEN * DMODEL];     // attention out, tf32-rounded
__device__ float g_h2  [T_LEN * DMODEL];
__device__ float g_h3  [T_LEN * DMODEL];     // exact (residual)
__device__ float g_h3t [T_LEN * DMODEL];     // rounded (GEMM A)
__device__ float g_gate[T_LEN * FF];         // h3t @ wg (raw)
__device__ float g_gb  [T_LEN * FF];         // silu(gate)*up, rounded
__device__ float g_rt  [T_LEN * 64];         // rope table: (cos,sin) x 32 per row

// ---------------------------------------------------------------------------
// helpers
// ---------------------------------------------------------------------------
__device__ __forceinline__ uint32_t smem_u32(const void* p) {
    uint32_t a;
    asm("{ .reg .u64 t; cvta.to.shared.u64 t, %1; cvt.u32.u64 %0, t; }" : "=r"(a) : "l"(p));
    return a;
}
__device__ __forceinline__ float to_tf32(float x) {
    asm("cvt.rna.tf32.f32 %0, %1;" : "=f"(x) : "f"(x));
    return x;
}
#define CP16(sm_addr, gptr) \
    asm volatile("cp.async.cg.shared.global [%0], [%1], 16;" :: "r"(sm_addr), "l"(gptr))
#define CP_COMMIT() asm volatile("cp.async.commit_group;")
#define CP_WAIT1()  asm volatile("cp.async.wait_group 1;")

__device__ __forceinline__ void mma_f(float* c, const float* a, const float* b) {
    asm volatile("mma.sync.aligned.m16n8k8.row.col.f32.tf32.tf32.f32 "
                 "{%0,%1,%2,%3}, {%4,%5,%6,%7}, {%8,%9}, {%0,%1,%2,%3};"
                 : "+f"(c[0]), "+f"(c[1]), "+f"(c[2]), "+f"(c[3])
                 : "r"(__float_as_uint(a[0])), "r"(__float_as_uint(a[1])),
                   "r"(__float_as_uint(a[2])), "r"(__float_as_uint(a[3])),
                   "r"(__float_as_uint(b[0])), "r"(__float_as_uint(b[1])));
}

// ---------------------------------------------------------------------------
// rope table: row t, d=0..31 -> (cos, sin)
// ---------------------------------------------------------------------------
__global__ __launch_bounds__(256) void rope_table_k(float* __restrict__ rt)
{
    int i = blockIdx.x * blockDim.x + threadIdx.x;   // over T*32
    int t = i >> 5, d = i & 31;
    double freq = exp((double)(-2.0 * d / 64.0) * 9.210340371976184);
    double si, co;
    sincos(freq * (double)t, &si, &co);
    ((float2*)rt)[i] = make_float2((float)co, (float)si);
}

// ---------------------------------------------------------------------------
// tf32 tensor-core GEMM: C[M,Nc] = A[M,K] @ Wsel[K, nsel]  (+add0 +add1)
// B streamed directly from row-major W (K-major global reads, coalesced).
// CTA 128x256, BK=16, 3-stage cp.async, 8 warps x (64x64).
// Three B sources for fused-QKV; epilogue: 0=none, 1=rope, 2=silu.
// ---------------------------------------------------------------------------
#define ASTRIDE 20
#define BSTRIDE 264
#define A_BYTES (128 * ASTRIDE * 4)          // 10240
#define B_BYTES (16 * BSTRIDE * 4)           // 16896
#define STG_B   (A_BYTES + B_BYTES)          // 27136
#define GSM_TOTAL (3 * STG_B)                // 81408

__global__ __launch_bounds__(256, 1) void tgemm_k(const float* __restrict__ A,
                                                  const float* __restrict__ B0,
                                                  const float* __restrict__ B1,
                                                  const float* __restrict__ B2,
                                                  float* __restrict__ C,
                                                  int M, int Nc, int K,
                                                  int sB0, int sB1, int sB2,
                                                  int blk1, int blk2,
                                                  const float* __restrict__ add0,
                                                  const float* __restrict__ add1,
                                                  int epi,
                                                  const float* __restrict__ epi_src)
{
    extern __shared__ char sm[];
    const uint32_t smb = smem_u32(sm);
    const int tid = threadIdx.x;
    const int wid = tid >> 5, lane = tid & 31;
    const int warp_m = wid & 1;
    const int warp_n = wid >> 1;
    const int bx = blockIdx.x;
    const int brow = blockIdx.y * 128;
    const int bcol = bx * 256;

    const float* B; int strideB, bcolB;
    if (bx < blk1)      { B = B0; strideB = sB0; bcolB = bx * 256; }
    else if (bx < blk2) { B = B1; strideB = sB1; bcolB = (bx - blk1) * 256; }
    else                { B = B2; strideB = sB2; bcolB = (bx - blk2) * 256; }

    // A loader: thread t -> row t>>1, cols (t&1)*8, 2x CP16
    const float* aG = A + (size_t)(brow + (tid >> 1)) * K + (tid & 1) * 8;
    const uint32_t sA0 = smb + (tid >> 1) * (ASTRIDE * 4) + (tid & 1) * 32;
    // B loader: thread t -> k-row t>>4, col chunk (t&15)*4, 4x CP16 at +64 floats
    const int bkr = tid >> 4, bc4 = (tid & 15) * 4;
    const float* bG = B + (size_t)bkr * strideB + bcolB + bc4;
    const uint32_t sB0a = smb + A_BYTES + (bkr * BSTRIDE + bc4) * 4;

    float c[4][8][4];
    #pragma unroll
    for (int mi = 0; mi < 4; mi++)
        #pragma unroll
        for (int ni = 0; ni < 8; ni++)
            #pragma unroll
            for (int j = 0; j < 4; j++) c[mi][ni][j] = 0.f;

    const int nk = K >> 4;

    #pragma unroll
    for (int p = 0; p < 2; p++) {
        const float* a0 = aG + p * 16;
        const float* b0 = bG + (size_t)p * 16 * strideB;
        uint32_t sa = sA0 + p * STG_B;
        uint32_t sb = sB0a + p * STG_B;
        CP16(sa, a0); CP16(sa + 16, a0 + 4);
        #pragma unroll
        for (int j = 0; j < 4; j++) CP16(sb + j * 256, b0 + j * 64);
        CP_COMMIT();
    }

    const int r1 = lane >> 2, cq = lane & 3;

    for (int kt = 0; kt < nk; kt++) {
        CP_WAIT1();
        __syncthreads();

        if (kt + 2 < nk) {
            int st = (kt + 2) % 3;
            const float* a0 = aG + (size_t)(kt + 2) * 16;
            const float* b0 = bG + (size_t)(kt + 2) * 16 * strideB;
            uint32_t sa = sA0 + st * STG_B;
            uint32_t sb = sB0a + st * STG_B;
            CP16(sa, a0); CP16(sa + 16, a0 + 4);
            #pragma unroll
            for (int j = 0; j < 4; j++) CP16(sb + j * 256, b0 + j * 64);
        }
        CP_COMMIT();

        const float* As = (const float*)(sm + (kt % 3) * STG_B);
        const float* Bs = As + A_BYTES / 4;
        const float* abase = As + (warp_m * 64 + r1) * ASTRIDE + cq;

        #pragma unroll
        for (int kk = 0; kk < 2; kk++) {
            float a[4][4], b[8][2];
            #pragma unroll
            for (int mi = 0; mi < 4; mi++) {
                const float* ap = abase + mi * 16 * ASTRIDE + kk * 8;
                a[mi][0] = ap[0];
                a[mi][1] = ap[8 * ASTRIDE];
                a[mi][2] = ap[4];
                a[mi][3] = ap[8 * ASTRIDE + 4];
            }
            const float* bp = Bs + (kk * 8 + cq) * BSTRIDE + warp_n * 64 + r1;
            #pragma unroll
            for (int ni = 0; ni < 8; ni++) {
                b[ni][0] = bp[ni * 8];
                b[ni][1] = bp[4 * BSTRIDE + ni * 8];
            }
            #pragma unroll
            for (int mi = 0; mi < 4; mi++)
                #pragma unroll
                for (int ni = 0; ni < 8; ni++)
                    mma_f(c[mi][ni], a[mi], b[ni]);
        }
    }

    // ---- epilogue ----
    #pragma unroll
    for (int mi = 0; mi < 4; mi++) {
        #pragma unroll
        for (int part = 0; part < 2; part++) {
            int r = brow + warp_m * 64 + mi * 16 + r1 + part * 8;
            size_t rowbase = (size_t)r * Nc;
            #pragma unroll
            for (int ni = 0; ni < 8; ni++) {
                int col = bcol + warp_n * 64 + ni * 8 + cq * 2;
                float2 v = make_float2(c[mi][ni][part * 2], c[mi][ni][part * 2 + 1]);
                if (epi == 1) {
                    if (col < 2560) {   // rope on q (0..2047) and k (2048..2559)
                        int dp = (col & 63) >> 1;
                        float2 cssn = ((const float2*)epi_src)[r * 32 + dp];
                        float x1 = v.x, x2 = v.y;
                        v.x = x1 * cssn.x - x2 * cssn.y;
                        v.y = x2 * cssn.x + x1 * cssn.y;
                    }
                } else if (epi == 2) {  // v = up; combine with gate
                    const float2 gt = *(const float2*)&epi_src[rowbase + col];
                    v.x = to_tf32(gt.x / (1.f + __expf(-gt.x)) * v.x);
                    v.y = to_tf32(gt.y / (1.f + __expf(-gt.y)) * v.y);
                }
                if (add0) { const float2 a2 = *(const float2*)&add0[rowbase + col];
                            v.x += a2.x; v.y += a2.y; }
                if (add1) { const float2 a2 = *(const float2*)&add1[rowbase + col];
                            v.x += a2.x; v.y += a2.y; }
                *(float2*)&C[rowbase + col] = v;
            }
        }
    }
}

// ---------------------------------------------------------------------------
// Tensor-core flash attention (causal GQA), unchanged from R5.
// ---------------------------------------------------------------------------
#define ATT_SMEM_FLOATS (4352 + 4352 + 4608 + 4352)
#define ATT_SMEM_BYTES  (ATT_SMEM_FLOATS * 4)

__global__ __launch_bounds__(128) void attn_tc_k(const float* __restrict__ QKV,
                                                 float* __restrict__ Oa)
{
    extern __shared__ float s[];
    float* qsm = s;                  // [64][68]
    float* ksm = s + 4352;           // [64][68]
    float* vsm = s + 8704;           // [64][72]
    float* psm = s + 13312;          // [4][16][68]

    const int tid = threadIdx.x;
    const int w = tid >> 5, lane = tid & 31;
    const int r1 = lane >> 2, cq = lane & 3;
    const int qt = blockIdx.x, h = blockIdx.y;
    const int kvh = h >> 2;

    {
        const float* qb = QKV + (size_t)(qt * 64) * QKV_N + h * HD;
        for (int t = tid; t < 1024; t += 128) {
            int i = t >> 4, d4 = (t & 15) * 4;
            float4 v4 = *(const float4*)(qb + (size_t)i * QKV_N + d4);
            v4.x = to_tf32(v4.x); v4.y = to_tf32(v4.y);
            v4.z = to_tf32(v4.z); v4.w = to_tf32(v4.w);
            *(float4*)(qsm + i * 68 + d4) = v4;
        }
    }
    __syncthreads();

    float qf[8][4];
    {
        const float* qb = qsm + (w * 16 + r1) * 68 + cq;
        #pragma unroll
        for (int ks = 0; ks < 8; ks++) {
            qf[ks][0] = qb[ks * 8];
            qf[ks][1] = qb[8 * 68 + ks * 8];
            qf[ks][2] = qb[ks * 8 + 4];
            qf[ks][3] = qb[8 * 68 + ks * 8 + 4];
        }
    }

    float oA[8][4];
    #pragma unroll
    for (int nt = 0; nt < 8; nt++)
        #pragma unroll
        for (int j = 0; j < 4; j++) oA[nt][j] = 0.f;
    float m0 = -1e30f, m1 = -1e30f, l0 = 0.f, l1 = 0.f;

    float* pb = psm + w * 16 * 68;

    for (int jt = 0; jt <= qt; jt++) {
        __syncthreads();
        {
            const float* kb = QKV + (size_t)(jt * 64) * QKV_N + DMODEL + kvh * HD;
            const float* vb = kb + 512;
            for (int t = tid; t < 1024; t += 128) {
                int i = t >> 4, d4 = (t & 15) * 4;
                float4 k4 = *(const float4*)(kb + (size_t)i * QKV_N + d4);
                k4.x = to_tf32(k4.x); k4.y = to_tf32(k4.y);
                k4.z = to_tf32(k4.z); k4.w = to_tf32(k4.w);
                *(float4*)(ksm + i * 68 + d4) = k4;
                float4 v4 = *(const float4*)(vb + (size_t)i * QKV_N + d4);
                v4.x = to_tf32(v4.x); v4.y = to_tf32(v4.y);
                v4.z = to_tf32(v4.z); v4.w = to_tf32(v4.w);
                *(float4*)(vsm + i * 72 + d4) = v4;
            }
        }
        __syncthreads();

        float sA[8][4];
        #pragma unroll
        for (int nt = 0; nt < 8; nt++) {
            float acc[4] = {0.f, 0.f, 0.f, 0.f};
            const float* kbp = ksm + (nt * 8 + r1) * 68 + cq;
            #pragma unroll
            for (int ks = 0; ks < 8; ks++) {
                float bf[2] = { kbp[ks * 8], kbp[ks * 8 + 4] };
                mma_f(acc, qf[ks], bf);
            }
            sA[nt][0] = acc[0]; sA[nt][1] = acc[1];
            sA[nt][2] = acc[2]; sA[nt][3] = acc[3];
        }

        float mn0 = m0, mn1 = m1;
        const int row0 = w * 16 + r1, row1 = row0 + 8;
        #pragma unroll
        for (int nt = 0; nt < 8; nt++) {
            #pragma unroll
            for (int j = 0; j < 4; j++) sA[nt][j] *= 0.125f;
            if (jt == qt) {
                int colb = nt * 8 + 2 * cq;
                if (colb     > row0) sA[nt][0] = -1e30f;
                if (colb + 1 > row0) sA[nt][1] = -1e30f;
                if (colb     > row1) sA[nt][2] = -1e30f;
                if (colb + 1 > row1) sA[nt][3] = -1e30f;
            }
            mn0 = fmaxf(mn0, fmaxf(sA[nt][0], sA[nt][1]));
            mn1 = fmaxf(mn1, fmaxf(sA[nt][2], sA[nt][3]));
        }
        mn0 = fmaxf(mn0, __shfl_xor_sync(0xffffffffu, mn0, 1));
        mn0 = fmaxf(mn0, __shfl_xor_sync(0xffffffffu, mn0, 2));
        mn1 = fmaxf(mn1, __shfl_xor_sync(0xffffffffu, mn1, 1));
        mn1 = fmaxf(mn1, __shfl_xor_sync(0xffffffffu, mn1, 2));

        float c0 = __expf(m0 - mn0), c1 = __expf(m1 - mn1);
        m0 = mn0; m1 = mn1;

        float ls0 = 0.f, ls1 = 0.f;
        #pragma unroll
        for (int nt = 0; nt < 8; nt++) {
            float p0 = to_tf32(__expf(sA[nt][0] - mn0));
            float p1 = to_tf32(__expf(sA[nt][1] - mn0));
            float p2 = to_tf32(__expf(sA[nt][2] - mn1));
            float p3 = to_tf32(__expf(sA[nt][3] - mn1));
            ls0 += p0 + p1; ls1 += p2 + p3;
            int cb = nt * 8 + 2 * cq;
            pb[r1 * 68 + cb]       = p0;
            pb[r1 * 68 + cb + 1]   = p1;
            pb[(r1 + 8) * 68 + cb]     = p2;
            pb[(r1 + 8) * 68 + cb + 1] = p3;
        }
        ls0 += __shfl_xor_sync(0xffffffffu, ls0, 1);
        ls0 += __shfl_xor_sync(0xffffffffu, ls0, 2);
        ls1 += __shfl_xor_sync(0xffffffffu, ls1, 1);
        ls1 += __shfl_xor_sync(0xffffffffu, ls1, 2);
        l0 = l0 * c0 + ls0;
        l1 = l1 * c1 + ls1;

        #pragma unroll
        for (int nt = 0; nt < 8; nt++) {
            oA[nt][0] *= c0; oA[nt][1] *= c0;
            oA[nt][2] *= c1; oA[nt][3] *= c1;
        }
        __syncwarp();

        #pragma unroll
        for (int ks = 0; ks < 8; ks++) {
            float af[4];
            af[0] = pb[r1 * 68 + ks * 8 + cq];
            af[1] = pb[(r1 + 8) * 68 + ks * 8 + cq];
            af[2] = pb[r1 * 68 + ks * 8 + cq + 4];
            af[3] = pb[(r1 + 8) * 68 + ks * 8 + cq + 4];
            const float* vb0 = vsm + (ks * 8 + cq) * 72 + r1;
            const float* vb1 = vsm + (ks * 8 + cq + 4) * 72 + r1;
            #pragma unroll
            for (int nt = 0; nt < 8; nt++) {
                float bf[2] = { vb0[nt * 8], vb1[nt * 8] };
                mma_f(oA[nt], af, bf);
            }
        }
    }

    float inv0 = 1.f / l0, inv1 = 1.f / l1;
    int gr0 = qt * 64 + w * 16 + r1;
    #pragma unroll
    for (int nt = 0; nt < 8; nt++) {
        int col = h * HD + nt * 8 + 2 * cq;
        float2 v0 = make_float2(to_tf32(oA[nt][0] * inv0), to_tf32(oA[nt][1] * inv0));
        float2 v1 = make_float2(to_tf32(oA[nt][2] * inv1), to_tf32(oA[nt][3] * inv1));
        *(float2*)&Oa[(size_t)gr0 * DMODEL + col] = v0;
        *(float2*)&Oa[(size_t)(gr0 + 8) * DMODEL + col] = v1;
    }
}

// ---------------------------------------------------------------------------
// RMSNorm: out exact, outT tf32-rounded
// ---------------------------------------------------------------------------
__global__ __launch_bounds__(256) void rmsnorm_k(const float* __restrict__ x,
                                                 const float* __restrict__ g,
                                                 float* __restrict__ out,
                                                 float* __restrict__ outT)
{
    int row = blockIdx.x;
    int tid = threadIdx.x;
    const float4* xr4 = (const float4*)(x + (size_t)row * DMODEL);
    const float4* g4  = (const float4*)g;

    float4 a = xr4[tid];
    float4 b = xr4[tid + 256];
    float s = a.x*a.x + a.y*a.y + a.z*a.z + a.w*a.w
            + b.x*b.x + b.y*b.y + b.z*b.z + b.w*b.w;
    #pragma unroll
    for (int off = 16; off > 0; off >>= 1) s += __shfl_xor_sync(0xffffffffu, s, off);

    __shared__ float red[8];
    __shared__ float inv_s;
    int wid = tid >> 5, lane = tid & 31;
    if (lane == 0) red[wid] = s;
    __syncthreads();
    if (tid == 0) {
        float t = 0.f;
        #pragma unroll
        for (int w = 0; w < 8; w++) t += red[w];
        inv_s = rsqrtf(t / (float)DMODEL + 1e-5f);
    }
    __syncthreads();
    float inv = inv_s;

    float4 ga = g4[tid], gb = g4[tid + 256];
    float4 ra, rb;
    ra.x = a.x*ga.x*inv; ra.y = a.y*ga.y*inv; ra.z = a.z*ga.z*inv; ra.w = a.w*ga.w*inv;
    rb.x = b.x*gb.x*inv; rb.y = b.y*gb.y*inv; rb.z = b.z*gb.z*inv; rb.w = b.w*gb.w*inv;
    ((float4*)(out + (size_t)row * DMODEL))[tid] = ra;
    ((float4*)(out + (size_t)row * DMODEL))[tid + 256] = rb;
    if (outT) {
        float4 ta = make_float4(to_tf32(ra.x), to_tf32(ra.y), to_tf32(ra.z), to_tf32(ra.w));
        float4 tb = make_float4(to_tf32(rb.x), to_tf32(rb.y), to_tf32(rb.z), to_tf32(rb.w));
        ((float4*)(outT + (size_t)row * DMODEL))[tid] = ta;
        ((float4*)(outT + (size_t)row * DMODEL))[tid + 256] = tb;
    }
}

// ---------------------------------------------------------------------------
// kernel_launch
// ---------------------------------------------------------------------------
extern "C" void kernel_launch(void* const* d_in, const int* in_sizes, int n_in,
                              void* d_out, int out_size)
{
    (void)in_sizes; (void)n_in; (void)out_size;
    const float* x  = (const float*)d_in[0];
    const float* g1 = (const float*)d_in[1];
    const float* wq = (const float*)d_in[2];
    const float* wk = (const float*)d_in[3];
    const float* wv = (const float*)d_in[4];
    const float* wo = (const float*)d_in[5];
    const float* g2 = (const float*)d_in[6];
    const float* wg = (const float*)d_in[7];
    const float* wu = (const float*)d_in[8];
    const float* wd = (const float*)d_in[9];
    float* out = (float*)d_out;

    float *xn, *xnt, *qkv, *att, *h2, *h3, *h3t, *gate, *gb, *rt;
    cudaGetSymbolAddress((void**)&xn,   g_xn);
    cudaGetSymbolAddress((void**)&xnt,  g_xnt);
    cudaGetSymbolAddress((void**)&qkv,  g_qkv);
    cudaGetSymbolAddress((void**)&att,  g_att);
    cudaGetSymbolAddress((void**)&h2,   g_h2);
    cudaGetSymbolAddress((void**)&h3,   g_h3);
    cudaGetSymbolAddress((void**)&h3t,  g_h3t);
    cudaGetSymbolAddress((void**)&gate, g_gate);
    cudaGetSymbolAddress((void**)&gb,   g_gb);
    cudaGetSymbolAddress((void**)&rt,   g_rt);

    cudaFuncSetAttribute(tgemm_k,   cudaFuncAttributeMaxDynamicSharedMemorySize, GSM_TOTAL);
    cudaFuncSetAttribute(attn_tc_k, cudaFuncAttributeMaxDynamicSharedMemorySize, ATT_SMEM_BYTES);

    // rope table + h1 = rmsnorm(x, g1)
    rope_table_k<<<T_LEN * 32 / 256, 256>>>(rt);
    rmsnorm_k<<<T_LEN, 256>>>(x, g1, xn, xnt);

    // qkv = h1t @ [wq|wk|wv], rope fused into epilogue
    tgemm_k<<<dim3(QKV_N/256, T_LEN/128), 256, GSM_TOTAL>>>(
        xnt, wq, wk, wv, qkv, T_LEN, QKV_N, DMODEL,
        DMODEL, 512, 512, 8, 10, nullptr, nullptr, 1, rt);

    attn_tc_k<<<dim3(T_LEN/64, NHEAD), 128, ATT_SMEM_BYTES>>>(qkv, att);

    // h2 = h1 + att @ wo
    tgemm_k<<<dim3(DMODEL/256, T_LEN/128), 256, GSM_TOTAL>>>(
        att, wo, wo, wo, h2, T_LEN, DMODEL, DMODEL,
        DMODEL, DMODEL, DMODEL, 9999, 9999, xn, nullptr, 0, nullptr);

    rmsnorm_k<<<T_LEN, 256>>>(h2, g2, h3, h3t);

    // gate = h3t @ wg
    tgemm_k<<<dim3(FF/256, T_LEN/128), 256, GSM_TOTAL>>>(
        h3t, wg, wg, wg, gate, T_LEN, FF, DMODEL,
        FF, FF, FF, 9999, 9999, nullptr, nullptr, 0, nullptr);

    // gb = tf32(silu(gate) * (h3t @ wu))   (silu fused into epilogue)
    tgemm_k<<<dim3(FF/256, T_LEN/128), 256, GSM_TOTAL>>>(
        h3t, wu, wu, wu, gb, T_LEN, FF, DMODEL,
        FF, FF, FF, 9999, 9999, nullptr, nullptr, 2, gate);

    // out = gb @ wd + h3 + x
    tgemm_k<<<dim3(DMODEL/256, T_LEN/128), 256, GSM_TOTAL>>>(
        gb, wd, wd, wd, out, T_LEN, DMODEL, FF,
        DMODEL, DMODEL, DMODEL, 9999, 9999, h3, x, 0, nullptr);
}